// round 6
// baseline (speedup 1.0000x reference)
#include <cuda_runtime.h>
#include <math.h>

#define T_STEPS 2048
#define L 1024
#define NB 128          // persistent blocks (<=148 SMs -> all co-resident)
#define JB 8            // columns per block (NB*JB == L)
#define NT 256          // 8 warps; warp w owns column b*JB + w
#define NREP 2          // replicas (spread L2 broadcast load)
#define SEGW 16         // floats per segment: 8 data + sentinel@[8] + pad
#define POISON_U 0xFFC00000u   // -NaN: sign bit set

// Static device scratch. Segment (t, rep, block): words 0-7 = the block's 8
// column values of a_t, word 8 = sentinel. Sentinels are write-once per
// replay (poison -> 1.0f); prep re-poisons them between replays.
__device__ float g_buf[T_STEPS][NREP][NB][SEGW];   // 32 MB
__device__ float g_gold;

// ---------------------------------------------------------------------------
// helpers: proven release/acquire protocol
// ---------------------------------------------------------------------------
__device__ __forceinline__ float ld_acq(const float* p) {
    float v;
    asm volatile("ld.acquire.gpu.global.f32 %0, [%1];" : "=f"(v) : "l"(p) : "memory");
    return v;
}
__device__ __forceinline__ void st_rel(float* p, float v) {
    asm volatile("st.release.gpu.global.f32 [%0], %1;" :: "l"(p), "f"(v) : "memory");
}
__device__ __forceinline__ void st_cg_v4(float* p, float4 v) {
    asm volatile("st.global.cg.v4.f32 [%0], {%1,%2,%3,%4};"
                 :: "l"(p), "f"(v.x), "f"(v.y), "f"(v.z), "f"(v.w) : "memory");
}
__device__ __forceinline__ float4 ld_cg_v4(const float* p) {
    float4 v;
    asm volatile("ld.global.cg.v4.f32 {%0,%1,%2,%3}, [%4];"
                 : "=f"(v.x), "=f"(v.y), "=f"(v.z), "=f"(v.w) : "l"(p) : "memory");
    return v;
}

// ---------------------------------------------------------------------------
// Prep: poison all sentinels (write-once discipline) + gold path score
// grid 2048 x 256 = 524288 threads = exactly one sentinel each
// ---------------------------------------------------------------------------
__global__ void crf_prep_kernel(const float* __restrict__ feats,
                                const float* __restrict__ transfer,
                                const int*   __restrict__ target) {
    unsigned n = blockIdx.x * blockDim.x + threadIdx.x;
    if (n < T_STEPS * NREP * NB) {
        ((unsigned*)g_buf)[n * SEGW + 8] = POISON_U;
    }

    if (blockIdx.x == 0) {
        int tid = threadIdx.x;
        float s = 0.f;
        for (int t = tid; t < T_STEPS; t += NT) {
            int lab = target[t];
            s += feats[t * L + lab];
            if (t < T_STEPS - 1) s += transfer[lab * L + target[t + 1]];
        }
        #pragma unroll
        for (int o = 16; o; o >>= 1) s += __shfl_xor_sync(0xffffffffu, s, o);
        __shared__ float red[NT / 32];
        if ((tid & 31) == 0) red[tid >> 5] = s;
        __syncthreads();
        if (tid == 0) {
            float tot = 0.f;
            #pragma unroll
            for (int w = 0; w < NT / 32; w++) tot += red[w];
            g_gold = tot;
        }
    }
}

// ---------------------------------------------------------------------------
// Persistent forward kernel, exp domain:
//   a_{t+1}[j] = (sum_i a_t[i]*E[i][j]) * exp(emit_{t+1}[j]) * 2^{-d_t}
//   d_t = ilogb(a_t[0])  -- read from identically-staged sa[0] in every block
//   log Z = ln(sum_j a_{T-1}[j]) + (sum_t d_t)*ln2
// Sync: one st.release sentinel per (block,rep) per step; each consumer
//       thread does ONE acquire poll then fetches its v4 under that acquire.
// ---------------------------------------------------------------------------
__global__ void __launch_bounds__(NT, 1)
crf_forward_kernel(const float* __restrict__ feats,
                   const float* __restrict__ transfer,
                   float* __restrict__ out) {
    __shared__ float sa[L];       // staged a_t
    __shared__ float sc[8];       // this block's 8 new column values
    __shared__ float sred[8];

    const int b    = blockIdx.x;
    const int tid  = threadIdx.x;
    const int w    = tid >> 5;
    const int lane = tid & 31;
    const int col  = b * JB + w;          // this warp's output column
    const int rep  = b & (NREP - 1);      // replica this block reads
    const int seg  = tid >> 1;            // segment this thread polls+fetches
    const int f4o  = (tid & 1) * 4;       // word offset inside segment

    // E column in registers: E[k].{x..w} = exp(transfer[i][col]), i=4*lane+128k+c
    float4 E[8];
    #pragma unroll
    for (int k = 0; k < 8; k++) {
        int i = lane * 4 + 128 * k;
        E[k].x = __expf(transfer[(i + 0) * L + col]);
        E[k].y = __expf(transfer[(i + 1) * L + col]);
        E[k].z = __expf(transfer[(i + 2) * L + col]);
        E[k].w = __expf(transfer[(i + 3) * L + col]);
    }

    // Bootstrap: publish a_0 = exp(feats[0]) for this block's 8 columns
    if (lane == 0) sc[w] = __expf(feats[col]);
    __syncthreads();
    if (tid == 0) {
        float4 lo = *(const float4*)&sc[0];
        float4 hi = *(const float4*)&sc[4];
        #pragma unroll
        for (int r = 0; r < NREP; r++) {
            st_cg_v4(&g_buf[0][r][b][0], lo);
            st_cg_v4(&g_buf[0][r][b][4], hi);
            st_rel(&g_buf[0][r][b][8], 1.0f);
        }
    }

    int K = 0;

    for (int t = 0; t < T_STEPS - 1; t++) {
        // off-critical-path: emission factor for this warp's column
        float exp_emit = __expf(__ldg(&feats[(t + 1) * L + col]));

        // ONE acquire poll on the sentinel of the segment we will fetch
        const float* sp = &g_buf[t][rep][seg][8];
        while (__float_as_int(ld_acq(sp)) < 0) { }
        // fetch this thread's 4 entries (ordered by our own acquire)
        float4 av = ld_cg_v4(&g_buf[t][rep][seg][f4o]);
        ((float4*)sa)[tid] = av;
        __syncthreads();                      // bar1: sa staged; sc reusable

        // consistent rescale exponent from the staged a_t[0] (identical
        // bitwise in every block -> no communication needed)
        int d = ((__float_as_int(sa[0]) >> 23) & 0xFF) - 127;
        K += d;
        float scale = __int_as_float((127 - d) << 23);   // exact 2^-d

        // mat-vec: warp w computes s = sum_i a_t[i] * E[i][col]
        float4 A = make_float4(0.f, 0.f, 0.f, 0.f);
        #pragma unroll
        for (int k = 0; k < 8; k++) {
            float4 aa = ((const float4*)sa)[lane + 32 * k];
            A.x = fmaf(aa.x, E[k].x, A.x);
            A.y = fmaf(aa.y, E[k].y, A.y);
            A.z = fmaf(aa.z, E[k].z, A.z);
            A.w = fmaf(aa.w, E[k].w, A.w);
        }
        float s = (A.x + A.y) + (A.z + A.w);
        #pragma unroll
        for (int o = 16; o; o >>= 1) s += __shfl_xor_sync(0xffffffffu, s, o);

        if (lane == 0) sc[w] = s * exp_emit * scale;
        __syncthreads();                      // bar2: sc complete

        if (tid == 0) {
            float4 lo = *(const float4*)&sc[0];
            float4 hi = *(const float4*)&sc[4];
            #pragma unroll
            for (int r = 0; r < NREP; r++) {
                st_cg_v4(&g_buf[t + 1][r][b][0], lo);
                st_cg_v4(&g_buf[t + 1][r][b][4], hi);
                st_rel(&g_buf[t + 1][r][b][8], 1.0f);
            }
        }
    }

    // Finalize: block 0 gathers a_{T-1} and writes the loss
    if (b == 0) {
        const float* sp = &g_buf[T_STEPS - 1][rep][seg][8];
        while (__float_as_int(ld_acq(sp)) < 0) { }
        float4 av = ld_cg_v4(&g_buf[T_STEPS - 1][rep][seg][f4o]);
        float s = (av.x + av.y) + (av.z + av.w);
        #pragma unroll
        for (int o = 16; o; o >>= 1) s += __shfl_xor_sync(0xffffffffu, s, o);
        if (lane == 0) sred[w] = s;
        __syncthreads();
        if (tid == 0) {
            float tot = 0.f;
            #pragma unroll
            for (int q = 0; q < 8; q++) tot += sred[q];
            double lz = log((double)tot) + (double)K * 0.69314718055994530942;
            out[0] = (float)(lz - (double)g_gold);
        }
    }
}

extern "C" void kernel_launch(void* const* d_in, const int* in_sizes, int n_in,
                              void* d_out, int out_size) {
    const float* feats    = (const float*)d_in[0];   // [2048, 1024] f32
    const float* transfer = (const float*)d_in[1];   // [1024, 1024] f32
    const int*   target   = (const int*)d_in[2];     // [2048] i32
    float* out = (float*)d_out;

    crf_prep_kernel<<<2048, NT>>>(feats, transfer, target);
    crf_forward_kernel<<<NB, NT>>>(feats, transfer, out);
}

// round 8
// speedup vs baseline: 1.5676x; 1.5676x over previous
#include <cuda_runtime.h>
#include <cuda_bf16.h>
#include <math.h>

#define T_STEPS 2048
#define L 1024
#define CSZ 16                 // cluster size (nonportable, opt-in)
#define CPC (L / CSZ)          // 64 columns per CTA
#define NT 256                 // 8 warps
#define NW 8
#define CPW (CPC / NW)         // 8 columns per warp

// E^T in bf16: g_E[col][i] = bf16(exp(transfer[i][col])). Built by prep.
__device__ __nv_bfloat16 g_E[L][L];     // 2 MB static

struct SmemLayout {
    float sa[2][L];                      // score vector, double-buffered (8 KB)
    float sgold[CSZ];                    // per-rank gold partials (rank 0 only)
    float sred[NW];
    __nv_bfloat16 E[CPC][L];             // this CTA's E slice (128 KB)
};

// ---------------------------------------------------------------------------
// helpers
// ---------------------------------------------------------------------------
__device__ __forceinline__ unsigned smem_u32(const void* p) {
    unsigned a;
    asm("{ .reg .u64 t; cvta.to.shared.u64 t, %1; cvt.u32.u64 %0, t; }"
        : "=r"(a) : "l"(p));
    return a;
}
__device__ __forceinline__ void st_cluster_f32(unsigned laddr, unsigned rank, float v) {
    unsigned ra;
    asm volatile("mapa.shared::cluster.u32 %0, %1, %2;" : "=r"(ra) : "r"(laddr), "r"(rank));
    asm volatile("st.shared::cluster.f32 [%0], %1;" :: "r"(ra), "f"(v) : "memory");
}
#define CLUSTER_SYNC() do { \
    asm volatile("barrier.cluster.arrive.aligned;" ::: "memory"); \
    asm volatile("barrier.cluster.wait.aligned;"   ::: "memory"); } while (0)

// ---------------------------------------------------------------------------
// Prep: g_E[c][i] = bf16(exp(transfer[i][c])) via smem-tiled transpose.
// grid 1024 x 256 (32x32 tiles); fully coalesced both sides.
// ---------------------------------------------------------------------------
__global__ void crf_prep_kernel(const float* __restrict__ transfer) {
    __shared__ float tile[32][33];
    int bi = blockIdx.x & 31;          // i-tile
    int bc = blockIdx.x >> 5;          // c-tile
    int tx = threadIdx.x & 31, ty = threadIdx.x >> 5;   // ty 0..7
    #pragma unroll
    for (int k = 0; k < 4; k++) {
        int i = bi * 32 + ty + 8 * k;
        tile[ty + 8 * k][tx] = transfer[i * L + bc * 32 + tx];
    }
    __syncthreads();
    #pragma unroll
    for (int k = 0; k < 4; k++) {
        int c = bc * 32 + ty + 8 * k;
        g_E[c][bi * 32 + tx] = __float2bfloat16(__expf(tile[tx][ty + 8 * k]));
    }
}

// ---------------------------------------------------------------------------
// Cluster forward kernel (exp domain):
//   a_{t+1}[j] = (sum_i a_t[i]*E[i][j]) * exp(emit_{t+1}[j]) * 2^{-d_t}
//   d_t = ilogb(a_t[0])  — identical bits in every CTA (same staged vector)
//   log Z = ln(sum_j a_{T-1}[j]) + (sum_t d_t)*ln2
// Sync: DSMEM push of 64 new values to all 16 CTAs + ONE cluster.sync/step.
// No global memory on the step critical path.
// ---------------------------------------------------------------------------
__global__ void __launch_bounds__(NT, 1)
crf_cluster_kernel(const float* __restrict__ feats,
                   const float* __restrict__ transfer,
                   const int*   __restrict__ target,
                   float* __restrict__ out) {
    extern __shared__ unsigned char smem_raw[];
    SmemLayout* sm = (SmemLayout*)smem_raw;

    const int tid  = threadIdx.x;
    const int w    = tid >> 5;
    const int lane = tid & 31;
    unsigned rank;
    asm("mov.u32 %0, %%cluster_ctarank;" : "=r"(rank));
    const int col0  = rank * CPC;          // CTA column base
    const int wcolg = col0 + w * CPW;      // warp column base (global)

    // --- prologue (off critical path, once per replay) ---
    // 1) copy E slice (128 KB) from gmem, coalesced
    {
        const uint4* src = (const uint4*)&g_E[col0][0];
        uint4* dst = (uint4*)&sm->E[0][0];
        for (int n = tid; n < CPC * L * 2 / 16; n += NT) dst[n] = src[n];
    }
    // 2) local a_0 = exp(feats[0]) (identical bits in every CTA)
    for (int n = tid; n < L; n += NT) sm->sa[0][n] = __expf(feats[n]);
    // 3) gold partial over t in [rank*128, rank*128+128), pushed to rank 0
    {
        float s = 0.f;
        int tbase = rank * (T_STEPS / CSZ);
        for (int t = tbase + tid; t < tbase + T_STEPS / CSZ; t += NT) {
            int lab = target[t];
            s += feats[t * L + lab];
            if (t < T_STEPS - 1) s += transfer[lab * L + target[t + 1]];
        }
        #pragma unroll
        for (int o = 16; o; o >>= 1) s += __shfl_xor_sync(0xffffffffu, s, o);
        if (lane == 0) sm->sred[w] = s;
        __syncthreads();
        if (tid == 0) {
            float g = 0.f;
            #pragma unroll
            for (int q = 0; q < NW; q++) g += sm->sred[q];
            st_cluster_f32(smem_u32(&sm->sgold[rank]), 0, g);
        }
    }
    CLUSTER_SYNC();   // cluster formed; E, a_0, gold partials all visible

    int K = 0;

    for (int t = 0; t < T_STEPS - 1; t++) {
        const int cur = t & 1, nxt = cur ^ 1;

        // emission factor for this lane's push column (8 distinct per warp)
        float emit = __expf(__ldg(&feats[(t + 1) * L + wcolg + (lane & 7)]));

        // stage a_t into registers (conflict-free float4)
        const float4* a4 = (const float4*)sm->sa[cur];
        float4 av[8];
        #pragma unroll
        for (int k = 0; k < 8; k++) av[k] = a4[lane + 32 * k];

        // consistent rescale exponent (identical bits in every CTA)
        int d = ((__float_as_int(sm->sa[cur][0]) >> 23) & 0xFF) - 127;
        K += d;
        float scale = __int_as_float((127 - d) << 23);   // exact 2^-d

        // 8 columns per warp: acc[c] = sum_i a[i] * E[i][col]
        float acc[CPW];
        #pragma unroll
        for (int c = 0; c < CPW; c++) acc[c] = 0.f;
        #pragma unroll
        for (int c = 0; c < CPW; c++) {
            const uint2* e2 = (const uint2*)&sm->E[w * CPW + c][0];
            #pragma unroll
            for (int k = 0; k < 8; k++) {
                uint2 e = e2[lane + 32 * k];    // 4 bf16 for i = 4lane+128k..+3
                acc[c] = fmaf(av[k].x, __int_as_float(e.x << 16),          acc[c]);
                acc[c] = fmaf(av[k].y, __int_as_float(e.x & 0xFFFF0000u),  acc[c]);
                acc[c] = fmaf(av[k].z, __int_as_float(e.y << 16),          acc[c]);
                acc[c] = fmaf(av[k].w, __int_as_float(e.y & 0xFFFF0000u),  acc[c]);
            }
        }

        // butterfly-reduce all 8 accumulators (every lane ends with all sums)
        #pragma unroll
        for (int o = 16; o; o >>= 1) {
            #pragma unroll
            for (int c = 0; c < CPW; c++)
                acc[c] += __shfl_xor_sync(0xffffffffu, acc[c], o);
        }

        // lane l pushes column (l&7) to ranks {l>>3, +4, +8, +12}
        float v = acc[0];
        #pragma unroll
        for (int c = 1; c < CPW; c++) if ((lane & 7) == c) v = acc[c];
        v = v * emit * scale;

        unsigned la = smem_u32(&sm->sa[nxt][wcolg + (lane & 7)]);
        unsigned r0 = lane >> 3;
        st_cluster_f32(la, r0,      v);
        st_cluster_f32(la, r0 + 4,  v);
        st_cluster_f32(la, r0 + 8,  v);
        st_cluster_f32(la, r0 + 12, v);

        CLUSTER_SYNC();   // release pushes / acquire for next step
    }

    // epilogue: rank 0 computes the loss (others exit; no more remote writes)
    if (rank == 0) {
        const float4* a4 = (const float4*)sm->sa[(T_STEPS - 1) & 1];
        float4 x = a4[tid];
        float s = (x.x + x.y) + (x.z + x.w);
        #pragma unroll
        for (int o = 16; o; o >>= 1) s += __shfl_xor_sync(0xffffffffu, s, o);
        if (lane == 0) sm->sred[w] = s;
        __syncthreads();
        if (tid == 0) {
            float tot = 0.f;
            #pragma unroll
            for (int q = 0; q < NW; q++) tot += sm->sred[q];
            float gold = 0.f;
            #pragma unroll
            for (int r = 0; r < CSZ; r++) gold += sm->sgold[r];
            double lz = log((double)tot) + (double)K * 0.69314718055994530942;
            out[0] = (float)(lz - (double)gold);
        }
    }
}

extern "C" void kernel_launch(void* const* d_in, const int* in_sizes, int n_in,
                              void* d_out, int out_size) {
    const float* feats    = (const float*)d_in[0];   // [2048, 1024] f32
    const float* transfer = (const float*)d_in[1];   // [1024, 1024] f32
    const int*   target   = (const int*)d_in[2];     // [2048] i32
    float* out = (float*)d_out;

    cudaFuncSetAttribute(crf_cluster_kernel,
                         cudaFuncAttributeMaxDynamicSharedMemorySize,
                         (int)sizeof(SmemLayout));
    cudaFuncSetAttribute(crf_cluster_kernel,
                         cudaFuncAttributeNonPortableClusterSizeAllowed, 1);

    crf_prep_kernel<<<1024, 256>>>(transfer);

    cudaLaunchConfig_t cfg = {};
    cfg.gridDim  = dim3(CSZ, 1, 1);
    cfg.blockDim = dim3(NT, 1, 1);
    cfg.dynamicSmemBytes = sizeof(SmemLayout);
    cfg.stream = 0;
    cudaLaunchAttribute attrs[1];
    attrs[0].id = cudaLaunchAttributeClusterDimension;
    attrs[0].val.clusterDim.x = CSZ;
    attrs[0].val.clusterDim.y = 1;
    attrs[0].val.clusterDim.z = 1;
    cfg.attrs = attrs;
    cfg.numAttrs = 1;

    cudaLaunchKernelEx(&cfg, crf_cluster_kernel, feats, transfer, target, out);
}

// round 10
// speedup vs baseline: 2.1966x; 1.4013x over previous
#include <cuda_runtime.h>
#include <cuda_bf16.h>
#include <math.h>

#define T_STEPS 2048
#define L 1024
#define CSZ 16                 // cluster size (nonportable, opt-in)
#define CPC (L / CSZ)          // 64 columns per CTA
#define NT 256                 // 8 warps
#define NW 8

// Packed exp(transfer), built by prep:
// g_Epack[k][lane][col] = uint2{ bf16x2(E[i0][col],E[i0+1][col]),
//                                bf16x2(E[i0+2][col],E[i0+3][col]) },
// i0 = 4*lane + 128*k.
__device__ uint2 g_Epack[8][32][L];   // 2 MB

// ---------------------------------------------------------------------------
// helpers
// ---------------------------------------------------------------------------
__device__ __forceinline__ unsigned smem_u32(const void* p) {
    unsigned a;
    asm("{ .reg .u64 t; cvta.to.shared.u64 t, %1; cvt.u32.u64 %0, t; }"
        : "=r"(a) : "l"(p));
    return a;
}
__device__ __forceinline__ void st_cluster_u32(unsigned laddr, unsigned rank, unsigned v) {
    unsigned ra;
    asm volatile("mapa.shared::cluster.u32 %0, %1, %2;" : "=r"(ra) : "r"(laddr), "r"(rank));
    asm volatile("st.shared::cluster.u32 [%0], %1;" :: "r"(ra), "r"(v) : "memory");
}
__device__ __forceinline__ void st_cluster_f32(unsigned laddr, unsigned rank, float v) {
    unsigned ra;
    asm volatile("mapa.shared::cluster.u32 %0, %1, %2;" : "=r"(ra) : "r"(laddr), "r"(rank));
    asm volatile("st.shared::cluster.f32 [%0], %1;" :: "r"(ra), "f"(v) : "memory");
}
#define CLUSTER_SYNC() do { \
    asm volatile("barrier.cluster.arrive.aligned;" ::: "memory"); \
    asm volatile("barrier.cluster.wait.aligned;"   ::: "memory"); } while (0)

__device__ __forceinline__ __nv_bfloat162 u2b(unsigned u) {
    return *reinterpret_cast<__nv_bfloat162*>(&u);
}
__device__ __forceinline__ unsigned b2u(__nv_bfloat162 b) {
    return *reinterpret_cast<unsigned*>(&b);
}

// ---------------------------------------------------------------------------
// Prep: build g_Epack (coalesced)
// ---------------------------------------------------------------------------
__global__ void crf_prep_E(const float* __restrict__ transfer) {
    int k = blockIdx.x >> 5, l = blockIdx.x & 31;
    int col = threadIdx.x;
    int i0 = 4 * l + 128 * k;
    float e0 = __expf(transfer[(i0 + 0) * L + col]);
    float e1 = __expf(transfer[(i0 + 1) * L + col]);
    float e2 = __expf(transfer[(i0 + 2) * L + col]);
    float e3 = __expf(transfer[(i0 + 3) * L + col]);
    __nv_bfloat162 p0 = __floats2bfloat162_rn(e0, e1);
    __nv_bfloat162 p1 = __floats2bfloat162_rn(e2, e3);
    g_Epack[k][l][col] = make_uint2(b2u(p0), b2u(p1));
}

// ---------------------------------------------------------------------------
// Cluster forward kernel (exp domain; bf16 state + HFMA2 matvec;
// fp32 reduction/epilogue per step):
//   a_{t+1}[j] = (sum_i a_t[i]*E[i][j]) * exp(emit_{t+1}[j]) * 2^{-d_t}
//   d_t = ilogb(a_t[0])  — identical bits in every CTA
//   log Z = ln(sum_j a_{T-1}[j]) + (sum_t d_t)*ln2
// ---------------------------------------------------------------------------
__global__ void __launch_bounds__(NT, 1)
crf_cluster_kernel(const float* __restrict__ feats,
                   const float* __restrict__ transfer,
                   const int*   __restrict__ target,
                   float* __restrict__ out) {
    __shared__ __nv_bfloat16 sa[2][L];    // 4 KB double-buffered state
    __shared__ float sgold[CSZ];
    __shared__ float sred[NW];

    const int tid  = threadIdx.x;
    const int w    = tid >> 5;
    const int lane = tid & 31;
    const int j    = lane & 3;            // word index (2 cols) this lane pushes
    unsigned rank;
    asm("mov.u32 %0, %%cluster_ctarank;" : "=r"(rank));
    const int col0 = rank * CPC;
    const int wcol = col0 + w * 8;        // warp's 8-column base (GLOBAL index)

    // --- E into registers: E[c][k][p] ---
    __nv_bfloat162 E[8][8][2];
    #pragma unroll
    for (int k = 0; k < 8; k++) {
        #pragma unroll
        for (int cp = 0; cp < 4; cp++) {
            uint4 q = *(const uint4*)&g_Epack[k][lane][wcol + 2 * cp];
            E[2 * cp + 0][k][0] = u2b(q.x);  E[2 * cp + 0][k][1] = u2b(q.y);
            E[2 * cp + 1][k][0] = u2b(q.z);  E[2 * cp + 1][k][1] = u2b(q.w);
        }
    }

    // --- bootstrap a_0 = exp(feats[0]) (identical bits in every CTA) ---
    for (int n = tid; n < L; n += NT)
        sa[0][n] = __float2bfloat16(__expf(feats[n]));

    // --- gold partial for t in [rank*128, (rank+1)*128), pushed to rank 0 ---
    {
        float s = 0.f;
        int tbase = rank * (T_STEPS / CSZ);
        for (int t = tbase + tid; t < tbase + T_STEPS / CSZ; t += NT) {
            int lab = target[t];
            s += feats[t * L + lab];
            if (t < T_STEPS - 1) s += transfer[lab * L + target[t + 1]];
        }
        #pragma unroll
        for (int o = 16; o; o >>= 1) s += __shfl_xor_sync(0xffffffffu, s, o);
        if (lane == 0) sred[w] = s;
        __syncthreads();
        if (tid == 0) {
            float g = 0.f;
            #pragma unroll
            for (int q = 0; q < NW; q++) g += sred[q];
            st_cluster_f32(smem_u32(&sgold[rank]), 0, g);
        }
    }
    CLUSTER_SYNC();   // E/a_0/gold visible cluster-wide

    int K = 0;
    const __nv_bfloat162 bz = __float2bfloat162_rn(0.f);

    // emission prefetch (cols 2j, 2j+1 of this warp), one step ahead
    float2 fpre = __ldg((const float2*)&feats[1 * L + wcol + 2 * j]);

    for (int t = 0; t < T_STEPS - 1; t++) {
        const int cur = t & 1, nxt = cur ^ 1;

        float2 fcur = fpre;
        int tn = (t + 2 < T_STEPS) ? (t + 2) : (T_STEPS - 1);
        fpre = __ldg((const float2*)&feats[tn * L + wcol + 2 * j]);

        // consistent rescale exponent from bf16 a_t[0] (identical everywhere)
        unsigned short us = __bfloat16_as_ushort(sa[cur][0]);
        int d = (int)((us >> 7) & 0xFF) - 127;
        K += d;
        float scale = __int_as_float((127 - d) << 23);   // exact 2^-d

        // emission * scale for this lane's 2 push columns (fp32)
        float emx = __expf(fcur.x) * scale;
        float emy = __expf(fcur.y) * scale;

        // --- matvec: 8 cols/warp, HFMA2 (chains of 8), E in regs ---
        __nv_bfloat162 acc[8][2];
        #pragma unroll
        for (int c = 0; c < 8; c++) { acc[c][0] = bz; acc[c][1] = bz; }
        #pragma unroll
        for (int k = 0; k < 8; k++) {
            uint2 a2 = *(const uint2*)&sa[cur][4 * lane + 128 * k];
            __nv_bfloat162 aA = u2b(a2.x), aB = u2b(a2.y);
            #pragma unroll
            for (int c = 0; c < 8; c++) {
                acc[c][0] = __hfma2(aA, E[c][k][0], acc[c][0]);
                acc[c][1] = __hfma2(aB, E[c][k][1], acc[c][1]);
            }
        }

        // per-col partial sums -> fp32, butterfly in fp32
        float cs[8];
        #pragma unroll
        for (int c = 0; c < 8; c++) {
            __nv_bfloat162 h = __hadd2(acc[c][0], acc[c][1]);
            cs[c] = __bfloat162float(__low2bfloat16(h)) +
                    __bfloat162float(__high2bfloat16(h));
        }
        #pragma unroll
        for (int o = 16; o; o >>= 1) {
            #pragma unroll
            for (int c = 0; c < 8; c++)
                cs[c] += __shfl_xor_sync(0xffffffffu, cs[c], o);
        }

        // select this lane's 2 columns, scale in fp32, pack to bf16x2
        float v0 = cs[0], v1 = cs[1];
        if (j == 1) { v0 = cs[2]; v1 = cs[3]; }
        if (j == 2) { v0 = cs[4]; v1 = cs[5]; }
        if (j == 3) { v0 = cs[6]; v1 = cs[7]; }
        unsigned val = b2u(__floats2bfloat162_rn(v0 * emx, v1 * emy));

        // push to GLOBAL slot col0 + 8w + 2j in two ranks' sa (pairs cover 16)
        unsigned la = smem_u32(&sa[nxt][col0 + 8 * w + 2 * j]);   // FIXED: +col0
        unsigned r0 = (unsigned)(lane >> 2) << 1;
        st_cluster_u32(la, r0,     val);
        st_cluster_u32(la, r0 + 1, val);

        CLUSTER_SYNC();   // release pushes / acquire for next step
    }

    // --- epilogue: rank 0 computes the loss ---
    if (rank == 0) {
        const int last = (T_STEPS - 1) & 1;
        uint2 a2 = *(const uint2*)&sa[last][4 * tid];
        __nv_bfloat162 x0 = u2b(a2.x), x1 = u2b(a2.y);
        float s = __bfloat162float(__low2bfloat16(x0)) +
                  __bfloat162float(__high2bfloat16(x0)) +
                  __bfloat162float(__low2bfloat16(x1)) +
                  __bfloat162float(__high2bfloat16(x1));
        #pragma unroll
        for (int o = 16; o; o >>= 1) s += __shfl_xor_sync(0xffffffffu, s, o);
        if (lane == 0) sred[w] = s;
        __syncthreads();
        if (tid == 0) {
            float tot = 0.f;
            #pragma unroll
            for (int q = 0; q < NW; q++) tot += sred[q];
            float gold = 0.f;
            #pragma unroll
            for (int r = 0; r < CSZ; r++) gold += sgold[r];
            double lz = log((double)tot) + (double)K * 0.69314718055994530942;
            out[0] = (float)(lz - (double)gold);
        }
    }
}

extern "C" void kernel_launch(void* const* d_in, const int* in_sizes, int n_in,
                              void* d_out, int out_size) {
    const float* feats    = (const float*)d_in[0];   // [2048, 1024] f32
    const float* transfer = (const float*)d_in[1];   // [1024, 1024] f32
    const int*   target   = (const int*)d_in[2];     // [2048] i32
    float* out = (float*)d_out;

    cudaFuncSetAttribute(crf_cluster_kernel,
                         cudaFuncAttributeNonPortableClusterSizeAllowed, 1);

    crf_prep_E<<<256, 1024>>>(transfer);

    cudaLaunchConfig_t cfg = {};
    cfg.gridDim  = dim3(CSZ, 1, 1);
    cfg.blockDim = dim3(NT, 1, 1);
    cfg.dynamicSmemBytes = 0;
    cfg.stream = 0;
    cudaLaunchAttribute attrs[1];
    attrs[0].id = cudaLaunchAttributeClusterDimension;
    attrs[0].val.clusterDim.x = CSZ;
    attrs[0].val.clusterDim.y = 1;
    attrs[0].val.clusterDim.z = 1;
    cfg.attrs = attrs;
    cfg.numAttrs = 1;

    cudaLaunchKernelEx(&cfg, crf_cluster_kernel, feats, transfer, target, out);
}

// round 11
// speedup vs baseline: 3.7780x; 1.7199x over previous
#include <cuda_runtime.h>
#include <cuda_bf16.h>
#include <math.h>

#define T_STEPS 2048
#define L 1024
#define CSZ 16                 // cluster size (nonportable, opt-in)
#define CPC (L / CSZ)          // 64 columns per CTA
#define NT 256                 // 8 warps
#define NW 8
#define TX_BYTES 2048u         // bytes landing in each CTA's sa[x] per step

// Packed exp(transfer), built by prep:
// g_Epack[k][lane][col] = uint2{ bf16x2(E[i0][col],E[i0+1][col]),
//                                bf16x2(E[i0+2][col],E[i0+3][col]) }, i0=4*lane+128*k
__device__ uint2 g_Epack[8][32][L];   // 2 MB

// ---------------------------------------------------------------------------
// helpers
// ---------------------------------------------------------------------------
__device__ __forceinline__ unsigned smem_u32(const void* p) {
    unsigned a;
    asm("{ .reg .u64 t; cvta.to.shared.u64 t, %1; cvt.u32.u64 %0, t; }"
        : "=r"(a) : "l"(p));
    return a;
}
__device__ __forceinline__ void st_cluster_f32(unsigned laddr, unsigned rank, float v) {
    unsigned ra;
    asm volatile("mapa.shared::cluster.u32 %0, %1, %2;" : "=r"(ra) : "r"(laddr), "r"(rank));
    asm volatile("st.shared::cluster.f32 [%0], %1;" :: "r"(ra), "f"(v) : "memory");
}
// async store with remote-mbarrier tx completion
__device__ __forceinline__ void st_async_u32(unsigned laddr, unsigned lmbar,
                                             unsigned rank, unsigned v) {
    unsigned ra, rm;
    asm volatile("mapa.shared::cluster.u32 %0, %1, %2;" : "=r"(ra) : "r"(laddr), "r"(rank));
    asm volatile("mapa.shared::cluster.u32 %0, %1, %2;" : "=r"(rm) : "r"(lmbar), "r"(rank));
    asm volatile("st.async.shared::cluster.mbarrier::complete_tx::bytes.b32 [%0], %1, [%2];"
                 :: "r"(ra), "r"(v), "r"(rm) : "memory");
}
__device__ __forceinline__ void mbar_init(unsigned mbar, unsigned count) {
    asm volatile("mbarrier.init.shared.b64 [%0], %1;" :: "r"(mbar), "r"(count) : "memory");
}
__device__ __forceinline__ void mbar_arm(unsigned mbar, unsigned bytes) {
    asm volatile("mbarrier.arrive.expect_tx.shared.b64 _, [%0], %1;"
                 :: "r"(mbar), "r"(bytes) : "memory");
}
__device__ __forceinline__ void mbar_wait(unsigned mbar, unsigned parity) {
    asm volatile(
        "{\n\t.reg .pred P;\n\t"
        "WAIT_%=:\n\t"
        "mbarrier.try_wait.parity.acquire.cluster.shared::cta.b64 P, [%0], %1;\n\t"
        "@!P bra WAIT_%=;\n\t"
        "}" :: "r"(mbar), "r"(parity) : "memory");
}
#define CLUSTER_SYNC() do { \
    asm volatile("barrier.cluster.arrive.aligned;" ::: "memory"); \
    asm volatile("barrier.cluster.wait.aligned;"   ::: "memory"); } while (0)

__device__ __forceinline__ __nv_bfloat162 u2b(unsigned u) {
    return *reinterpret_cast<__nv_bfloat162*>(&u);
}
__device__ __forceinline__ unsigned b2u(__nv_bfloat162 b) {
    return *reinterpret_cast<unsigned*>(&b);
}

// ---------------------------------------------------------------------------
// Prep: build g_Epack (coalesced)
// ---------------------------------------------------------------------------
__global__ void crf_prep_E(const float* __restrict__ transfer) {
    int k = blockIdx.x >> 5, l = blockIdx.x & 31;
    int col = threadIdx.x;
    int i0 = 4 * l + 128 * k;
    float e0 = __expf(transfer[(i0 + 0) * L + col]);
    float e1 = __expf(transfer[(i0 + 1) * L + col]);
    float e2 = __expf(transfer[(i0 + 2) * L + col]);
    float e3 = __expf(transfer[(i0 + 3) * L + col]);
    g_Epack[k][l][col] = make_uint2(b2u(__floats2bfloat162_rn(e0, e1)),
                                    b2u(__floats2bfloat162_rn(e2, e3)));
}

// ---------------------------------------------------------------------------
// Cluster forward kernel: bf16 state/HFMA2 matvec, fp32 folded reduction,
// st.async pushes + per-CTA mbarrier tx counting. No per-step barriers.
// ---------------------------------------------------------------------------
__global__ void __launch_bounds__(NT, 1)
crf_cluster_kernel(const float* __restrict__ feats,
                   const float* __restrict__ transfer,
                   const int*   __restrict__ target,
                   float* __restrict__ out) {
    __shared__ __nv_bfloat16 sa[2][L];                 // 4 KB double-buffered state
    __shared__ __align__(8) unsigned long long smbar[2];
    __shared__ float sgold[CSZ];
    __shared__ float sred[NW];

    const int tid  = threadIdx.x;
    const int w    = tid >> 5;
    const int lane = tid & 31;
    const int bit4 = (lane >> 4) & 1;
    const int bit3 = (lane >> 3) & 1;
    const int q    = 2 * bit4 + bit3;      // this lane's push word (cols 2q,2q+1)
    unsigned rank;
    asm("mov.u32 %0, %%cluster_ctarank;" : "=r"(rank));
    const int col0 = rank * CPC;
    const int wcol = col0 + w * 8;         // warp's 8-column base (global)

    const unsigned mb0 = smem_u32(&smbar[0]);
    const unsigned mb1 = smem_u32(&smbar[1]);

    // --- E into registers: E[c][k][p] ---
    __nv_bfloat162 E[8][8][2];
    #pragma unroll
    for (int k = 0; k < 8; k++) {
        #pragma unroll
        for (int cp = 0; cp < 4; cp++) {
            uint4 t4 = *(const uint4*)&g_Epack[k][lane][wcol + 2 * cp];
            E[2 * cp + 0][k][0] = u2b(t4.x);  E[2 * cp + 0][k][1] = u2b(t4.y);
            E[2 * cp + 1][k][0] = u2b(t4.z);  E[2 * cp + 1][k][1] = u2b(t4.w);
        }
    }

    // --- mbarriers: init + arm both (before cluster sync) ---
    if (tid == 0) {
        mbar_init(mb0, 1);
        mbar_init(mb1, 1);
        mbar_arm(mb0, TX_BYTES);
        mbar_arm(mb1, TX_BYTES);
    }

    // --- bootstrap a_0 = exp(feats[0]) (identical bits in every CTA) ---
    for (int n = tid; n < L; n += NT)
        sa[0][n] = __float2bfloat16(__expf(feats[n]));

    // --- gold partial for t in [rank*128, (rank+1)*128), pushed to rank 0 ---
    {
        float s = 0.f;
        int tbase = rank * (T_STEPS / CSZ);
        for (int t = tbase + tid; t < tbase + T_STEPS / CSZ; t += NT) {
            int lab = target[t];
            s += feats[t * L + lab];
            if (t < T_STEPS - 1) s += transfer[lab * L + target[t + 1]];
        }
        #pragma unroll
        for (int o = 16; o; o >>= 1) s += __shfl_xor_sync(0xffffffffu, s, o);
        if (lane == 0) sred[w] = s;
        __syncthreads();
        if (tid == 0) {
            float g = 0.f;
            #pragma unroll
            for (int qq = 0; qq < NW; qq++) g += sred[qq];
            st_cluster_f32(smem_u32(&sgold[rank]), 0, g);
        }
    }
    CLUSTER_SYNC();   // E regs / a_0 / gold / mbarrier init visible cluster-wide

    int K = 0;
    int ph0 = 0, ph1 = 0;                  // mbarrier phase parities
    const __nv_bfloat162 bz = __float2bfloat162_rn(0.f);

    // emission prefetch for this lane's 2 push columns, one step ahead
    float2 fpre = __ldg((const float2*)&feats[1 * L + wcol + 2 * q]);

    for (int t = 0; t < T_STEPS - 1; t++) {
        const int cur = t & 1, nxt = cur ^ 1;

        float2 fcur = fpre;
        int tn = (t + 2 < T_STEPS) ? (t + 2) : (T_STEPS - 1);
        fpre = __ldg((const float2*)&feats[tn * L + wcol + 2 * q]);

        // wait for buffer cur to be fully delivered (t=0: local bootstrap)
        if (t > 0) {
            if (cur) { mbar_wait(mb1, ph1); ph1 ^= 1; }
            else     { mbar_wait(mb0, ph0); ph0 ^= 1; }
            if (tid == 0) mbar_arm(cur ? mb1 : mb0, TX_BYTES);  // re-arm next phase
        }

        // consistent rescale exponent from bf16 a_t[0] (identical everywhere)
        unsigned short us = __bfloat16_as_ushort(sa[cur][0]);
        int d = (int)((us >> 7) & 0xFF) - 127;
        K += d;
        float scale = __int_as_float((127 - d) << 23);   // exact 2^-d

        float emx = __expf(fcur.x) * scale;
        float emy = __expf(fcur.y) * scale;

        // --- matvec: 8 cols/warp, HFMA2 (chains of 8), E in regs ---
        __nv_bfloat162 acc[8][2];
        #pragma unroll
        for (int c = 0; c < 8; c++) { acc[c][0] = bz; acc[c][1] = bz; }
        #pragma unroll
        for (int k = 0; k < 8; k++) {
            uint2 a2 = *(const uint2*)&sa[cur][4 * lane + 128 * k];
            __nv_bfloat162 aA = u2b(a2.x), aB = u2b(a2.y);
            #pragma unroll
            for (int c = 0; c < 8; c++) {
                acc[c][0] = __hfma2(aA, E[c][k][0], acc[c][0]);
                acc[c][1] = __hfma2(aB, E[c][k][1], acc[c][1]);
            }
        }

        // per-col chunk sums -> fp32
        float cs[8];
        #pragma unroll
        for (int c = 0; c < 8; c++) {
            __nv_bfloat162 h = __hadd2(acc[c][0], acc[c][1]);
            cs[c] = __bfloat162float(__low2bfloat16(h)) +
                    __bfloat162float(__high2bfloat16(h));
        }

        // folded reduction: 8 -> 4 regs (xor16), 4 -> 2 (xor8), butterfly x3
        float n0, n1, n2, n3;
        {
            float s0 = bit4 ? cs[0] : cs[4], k0 = bit4 ? cs[4] : cs[0];
            float s1 = bit4 ? cs[1] : cs[5], k1 = bit4 ? cs[5] : cs[1];
            float s2 = bit4 ? cs[2] : cs[6], k2 = bit4 ? cs[6] : cs[2];
            float s3 = bit4 ? cs[3] : cs[7], k3 = bit4 ? cs[7] : cs[3];
            n0 = k0 + __shfl_xor_sync(0xffffffffu, s0, 16);
            n1 = k1 + __shfl_xor_sync(0xffffffffu, s1, 16);
            n2 = k2 + __shfl_xor_sync(0xffffffffu, s2, 16);
            n3 = k3 + __shfl_xor_sync(0xffffffffu, s3, 16);
        }
        float v0, v1;
        {
            float s0 = bit3 ? n0 : n2, k0 = bit3 ? n2 : n0;
            float s1 = bit3 ? n1 : n3, k1 = bit3 ? n3 : n1;
            v0 = k0 + __shfl_xor_sync(0xffffffffu, s0, 8);
            v1 = k1 + __shfl_xor_sync(0xffffffffu, s1, 8);
        }
        #pragma unroll
        for (int o = 4; o; o >>= 1) {
            v0 += __shfl_xor_sync(0xffffffffu, v0, o);
            v1 += __shfl_xor_sync(0xffffffffu, v1, o);
        }
        // lane now owns cols wcol+2q, wcol+2q+1 summed over all 32 lanes

        unsigned val = b2u(__floats2bfloat162_rn(v0 * emx, v1 * emy));

        // async push to 2 ranks; tx counts into each target's mbar[nxt]
        unsigned la = smem_u32(&sa[nxt][col0 + 8 * w + 2 * q]);
        unsigned lm = nxt ? mb1 : mb0;
        unsigned r0 = (unsigned)(lane & 7) * 2;
        st_async_u32(la, lm, r0,     val);
        st_async_u32(la, lm, r0 + 1, val);
    }

    // final buffer fully delivered before any CTA may exit
    {
        const int last = (T_STEPS - 1) & 1;
        if (last) mbar_wait(mb1, ph1);
        else      mbar_wait(mb0, ph0);
    }

    // --- epilogue: rank 0 computes the loss ---
    if (rank == 0) {
        const int last = (T_STEPS - 1) & 1;
        uint2 a2 = *(const uint2*)&sa[last][4 * tid];
        __nv_bfloat162 x0 = u2b(a2.x), x1 = u2b(a2.y);
        float s = __bfloat162float(__low2bfloat16(x0)) +
                  __bfloat162float(__high2bfloat16(x0)) +
                  __bfloat162float(__low2bfloat16(x1)) +
                  __bfloat162float(__high2bfloat16(x1));
        #pragma unroll
        for (int o = 16; o; o >>= 1) s += __shfl_xor_sync(0xffffffffu, s, o);
        if (lane == 0) sred[w] = s;
        __syncthreads();
        if (tid == 0) {
            float tot = 0.f;
            #pragma unroll
            for (int qq = 0; qq < NW; qq++) tot += sred[qq];
            float gold = 0.f;
            #pragma unroll
            for (int r = 0; r < CSZ; r++) gold += sgold[r];
            double lz = log((double)tot) + (double)K * 0.69314718055994530942;
            out[0] = (float)(lz - (double)gold);
        }
    }
}

extern "C" void kernel_launch(void* const* d_in, const int* in_sizes, int n_in,
                              void* d_out, int out_size) {
    const float* feats    = (const float*)d_in[0];   // [2048, 1024] f32
    const float* transfer = (const float*)d_in[1];   // [1024, 1024] f32
    const int*   target   = (const int*)d_in[2];     // [2048] i32
    float* out = (float*)d_out;

    cudaFuncSetAttribute(crf_cluster_kernel,
                         cudaFuncAttributeNonPortableClusterSizeAllowed, 1);

    crf_prep_E<<<256, 1024>>>(transfer);

    cudaLaunchConfig_t cfg = {};
    cfg.gridDim  = dim3(CSZ, 1, 1);
    cfg.blockDim = dim3(NT, 1, 1);
    cfg.dynamicSmemBytes = 0;
    cfg.stream = 0;
    cudaLaunchAttribute attrs[1];
    attrs[0].id = cudaLaunchAttributeClusterDimension;
    attrs[0].val.clusterDim.x = CSZ;
    attrs[0].val.clusterDim.y = 1;
    attrs[0].val.clusterDim.z = 1;
    cfg.attrs = attrs;
    cfg.numAttrs = 1;

    cudaLaunchKernelEx(&cfg, crf_cluster_kernel, feats, transfer, target, out);
}